// round 15
// baseline (speedup 1.0000x reference)
#include <cuda_runtime.h>
#include <cuda_bf16.h>
#include <cstdint>

#define LEN_HIS 20
#define D_IN    36
#define HID     64
#define G3      192
#define DIM_C   4
#define MAXN    32768
#define M_TILE  128     // timesteps per block; 4 warps x 2 streams x 16 rows

// ---------------- scratch ----------------
__device__ float g_GI[MAXN * G3];   // b_ih + b_hh(r,z) folded in
__device__ int   g_start[MAXN];

// ---------------- smem layout (bytes) ----------------
// GRU loop: Whh_hi @0 (24KB), Whh_lo @24KB (24KB), hbuf @48KB (32KB).
// After loop: W1_hi @0 (8KB), W1_lo @8KB (re-staged into dead Whh region).
#define OFF_WHH_HI 0
#define OFF_WHH_LO 24576
#define OFF_HBUF   49152
#define OFF_W1_HI  0
#define OFF_W1_LO  8192
#define SMEM_SZ    81920

#define SWZ(o) ((o) ^ (((o) >> 3) & 0x70))

// ---------------- helpers ----------------
__device__ __forceinline__ float sigmoidf_(float x) {
    return __fdividef(1.0f, 1.0f + __expf(-x));
}
__device__ __forceinline__ float tanhf_(float x) {
    return __fdividef(2.0f, 1.0f + __expf(-2.0f * x)) - 1.0f;
}
__device__ __forceinline__ uint32_t smem_u32(const void* p) {
    uint32_t a;
    asm("{ .reg .u64 t; cvta.to.shared.u64 t, %1; cvt.u32.u64 %0, t; }" : "=r"(a) : "l"(p));
    return a;
}
__device__ __forceinline__ void ldsm4(uint32_t* r, uint32_t addr) {
    asm volatile("ldmatrix.sync.aligned.m8n8.x4.shared.b16 {%0,%1,%2,%3}, [%4];"
        : "=r"(r[0]), "=r"(r[1]), "=r"(r[2]), "=r"(r[3]) : "r"(addr));
}
__device__ __forceinline__ void mma16816(float* d, const uint32_t* a, uint32_t b0, uint32_t b1) {
    asm volatile("mma.sync.aligned.m16n8k16.row.col.f32.bf16.bf16.f32 "
        "{%0,%1,%2,%3}, {%4,%5,%6,%7}, {%8,%9}, {%0,%1,%2,%3};"
        : "+f"(d[0]), "+f"(d[1]), "+f"(d[2]), "+f"(d[3])
        : "r"(a[0]), "r"(a[1]), "r"(a[2]), "r"(a[3]), "r"(b0), "r"(b1));
}
// bf16 split with truncation (x = hi + r exactly; lo = bf16(r) -> ~2^-17 total)
__device__ __forceinline__ void split_pack(float x, float y, uint32_t& hi, uint32_t& lo) {
    uint32_t fx = __float_as_uint(x), fy = __float_as_uint(y);
    hi = (fy & 0xffff0000u) | (fx >> 16);
    float lx = x - __uint_as_float(fx & 0xffff0000u);
    float ly = y - __uint_as_float(fy & 0xffff0000u);
    uint32_t flx = __float_as_uint(lx), fly = __float_as_uint(ly);
    lo = (fly & 0xffff0000u) | (flx >> 16);
}
__device__ __forceinline__ float unpk_lo(uint32_t u) { return __uint_as_float(u << 16); }
__device__ __forceinline__ float unpk_hi(uint32_t u) { return __uint_as_float(u & 0xffff0000u); }

// ---------------------------------------------------------------------------
// Kernel A: GI[t][j] = b_ih[j] + (j<128 ? b_hh[j] : 0) + emb[t] . W_ih[j]
//           plus window starts.
// ---------------------------------------------------------------------------
__global__ void __launch_bounds__(192) precompute_kernel(
    const float* __restrict__ emb, const float* __restrict__ W_ih,
    const float* __restrict__ b_ih, const float* __restrict__ b_hh,
    const int* __restrict__ dones, int n)
{
    __shared__ float sW[D_IN * G3];
    __shared__ float sX[64 * D_IN];
    const int tid = threadIdx.x;
    const int t0  = blockIdx.x * 64;

    for (int idx = tid; idx < G3 * D_IN; idx += 192) {
        int j = idx / D_IN, k = idx % D_IN;
        sW[k * G3 + j] = W_ih[idx];
    }
    const int nt = min(64, n - t0);
    for (int idx = tid; idx < nt * D_IN; idx += 192)
        sX[idx] = emb[t0 * D_IN + idx];
    __syncthreads();

    const float bj = b_ih[tid] + (tid < 128 ? b_hh[tid] : 0.f);
    for (int tt = 0; tt < nt; ++tt) {
        float a0 = bj, a1 = 0.f, a2 = 0.f, a3 = 0.f;
        const float* x = &sX[tt * D_IN];
        #pragma unroll
        for (int k = 0; k < 36; k += 4) {
            a0 = fmaf(sW[(k + 0) * G3 + tid], x[k + 0], a0);
            a1 = fmaf(sW[(k + 1) * G3 + tid], x[k + 1], a1);
            a2 = fmaf(sW[(k + 2) * G3 + tid], x[k + 2], a2);
            a3 = fmaf(sW[(k + 3) * G3 + tid], x[k + 3], a3);
        }
        g_GI[(t0 + tt) * G3 + tid] = (a0 + a1) + (a2 + a3);
    }

    if (tid < 64) {
        int t = t0 + tid;
        if (t < n) {
            int s = t - (LEN_HIS - 1);
            if (s < 0) s = 0;
            int st = s;
            for (int k = s; k < t; ++k)
                if (dones[k] != 0) st = k + 1;
            g_start[t] = st;
        }
    }
}

// ---------------------------------------------------------------------------
// Kernel B: dual-stream warp-MMA batched GRU. Each warp owns TWO independent
// 16-timestep streams (64 apart). One ldmatrix of W_hh feeds both streams'
// MMAs; MMAs alternate streams (acc dep dist 2); the elementwise phase gets
// 2x independent MUFU/FFMA chains. New h lives in a thread-private smem
// double buffer (stream 0 = words 0..31, stream 1 = words 32..63;
// conflict-free, no sync). No forced occupancy caps.
// ---------------------------------------------------------------------------
__global__ void __launch_bounds__(128) gru_mma_kernel(
    const float* __restrict__ Whh, const float* __restrict__ bhh,
    const float* __restrict__ W1,  const float* __restrict__ b1,
    const float* __restrict__ W2,  const float* __restrict__ b2,
    float* __restrict__ out, int n)
{
    extern __shared__ __align__(1024) char smem[];
    const int tid = threadIdx.x;
    const int l   = tid & 31;
    const int w   = tid >> 5;

    // stage Whh (192x64) hi/lo, SW128-swizzled 128B rows
    for (int i = tid; i < G3 * HID; i += 128) {
        float v = Whh[i];
        int row = i >> 6, col = i & 63;
        uint32_t off = SWZ((uint32_t)(row * 128 + col * 2));
        __nv_bfloat16 hi = __float2bfloat16(v);
        __nv_bfloat16 lo = __float2bfloat16(v - __bfloat162float(hi));
        *reinterpret_cast<__nv_bfloat16*>(smem + OFF_WHH_HI + off) = hi;
        *reinterpret_cast<__nv_bfloat16*>(smem + OFF_WHH_LO + off) = lo;
    }
    __syncthreads();

    const uint32_t sb = smem_u32(smem);
    const int c2 = (l & 3) * 2;                   // col pair within 8-wide tile
    const int tb = blockIdx.x * M_TILE + w * 16 + (l >> 2);
    const int t00 = tb,      t01 = tb + 8;        // stream 0 rows
    const int t10 = tb + 64, t11 = tb + 72;       // stream 1 rows
    const int s00 = (t00 < n) ? g_start[t00] : 0;
    const int s01 = (t01 < n) ? g_start[t01] : 0;
    const int s10 = (t10 < n) ? g_start[t10] : 0;
    const int s11 = (t11 < n) ? g_start[t11] : 0;

    int f00 = (t00 < n) ? max(0, s00 - t00 + (LEN_HIS - 1)) : LEN_HIS;
    int f01 = (t01 < n) ? max(0, s01 - t01 + (LEN_HIS - 1)) : LEN_HIS;
    int f10 = (t10 < n) ? max(0, s10 - t10 + (LEN_HIS - 1)) : LEN_HIS;
    int f11 = (t11 < n) ? max(0, s11 - t11 + (LEN_HIS - 1)) : LEN_HIS;
    const int warp_first = __reduce_min_sync(0xffffffffu,
                                             min(min(f00, f01), min(f10, f11)));

    const int bn_row = (l & 7);
    const int bn_k   = (l >> 3) * 8;

    // thread-private new-h buffer: word-major [64 words][128 threads]
    uint32_t* hb = reinterpret_cast<uint32_t*>(smem + OFF_HBUF) + tid;
    const float* bhn_base = &bhh[2 * HID + c2];

    // hidden-state A fragments per stream: [k-tile 0..3][a0..a3], bf16x2
    uint32_t ah0[4][4], al0[4][4], ah1[4][4], al1[4][4];
    #pragma unroll
    for (int i = 0; i < 4; ++i)
        #pragma unroll
        for (int jx = 0; jx < 4; ++jx) {
            ah0[i][jx] = 0u; al0[i][jx] = 0u;
            ah1[i][jx] = 0u; al1[i][jx] = 0u;
        }

    for (int step = warp_first; step < LEN_HIS; ++step) {
        const int d = -(LEN_HIS - 1) + step;
        const int g00 = t00 + d, g01 = t01 + d, g10 = t10 + d, g11 = t11 + d;
        const bool v00 = (t00 < n) && (g00 >= s00);
        const bool v01 = (t01 < n) && (g01 >= s01);
        const bool v10 = (t10 < n) && (g10 >= s10);
        const bool v11 = (t11 < n) && (g11 >= s11);
        const float* gp00 = &g_GI[(v00 ? g00 : 0) * G3 + c2];
        const float* gp01 = &g_GI[(v01 ? g01 : 0) * G3 + c2];
        const float* gp10 = &g_GI[(v10 ? g10 : 0) * G3 + c2];
        const float* gp11 = &g_GI[(v11 ? g11 : 0) * G3 + c2];

        #pragma unroll
        for (int ntg = 0; ntg < 8; ++ntg) {
            float acc0[3][4], acc1[3][4];
            #pragma unroll
            for (int gi = 0; gi < 3; ++gi)
                #pragma unroll
                for (int ci = 0; ci < 4; ++ci) { acc0[gi][ci] = 0.f; acc1[gi][ci] = 0.f; }

            #pragma unroll
            for (int gate = 0; gate < 3; ++gate) {
                const int nt = gate * 8 + ntg;
                #pragma unroll
                for (int kh = 0; kh < 2; ++kh) {
                    uint32_t bh[4], bl[4];
                    uint32_t boff = SWZ((uint32_t)((nt * 8 + bn_row) * 128 + (kh * 32 + bn_k) * 2));
                    ldsm4(bh, sb + OFF_WHH_HI + boff);
                    ldsm4(bl, sb + OFF_WHH_LO + boff);
                    #pragma unroll
                    for (int k2 = 0; k2 < 2; ++k2) {
                        const int kt = kh * 2 + k2;
                        mma16816(acc0[gate], ah0[kt], bh[k2 * 2], bh[k2 * 2 + 1]);
                        mma16816(acc1[gate], ah1[kt], bh[k2 * 2], bh[k2 * 2 + 1]);
                        mma16816(acc0[gate], al0[kt], bh[k2 * 2], bh[k2 * 2 + 1]);
                        mma16816(acc1[gate], al1[kt], bh[k2 * 2], bh[k2 * 2 + 1]);
                        mma16816(acc0[gate], ah0[kt], bl[k2 * 2], bl[k2 * 2 + 1]);
                        mma16816(acc1[gate], ah1[kt], bl[k2 * 2], bl[k2 * 2 + 1]);
                    }
                }
            }

            const int kt = ntg >> 1;
            const int sl = (ntg & 1) * 2;
            const float2 bhnv = __ldg(reinterpret_cast<const float2*>(bhn_base + 8 * ntg));

            // ---- stream 0 update (words 0..31) ----
            #pragma unroll
            for (int rh = 0; rh < 2; ++rh) {
                const bool vv = rh ? v01 : v00;
                const float* gp = rh ? gp01 : gp00;
                const int slot = sl + rh;
                float hx = unpk_lo(ah0[kt][slot]) + unpk_lo(al0[kt][slot]);
                float hy = unpk_hi(ah0[kt][slot]) + unpk_hi(al0[kt][slot]);
                if (vv) {
                    float2 gr = *reinterpret_cast<const float2*>(gp + 8 * ntg);
                    float2 gz = *reinterpret_cast<const float2*>(gp + HID + 8 * ntg);
                    float2 gn = *reinterpret_cast<const float2*>(gp + 2 * HID + 8 * ntg);
                    float r0 = sigmoidf_(gr.x + acc0[0][rh * 2]);
                    float r1 = sigmoidf_(gr.y + acc0[0][rh * 2 + 1]);
                    float z0 = sigmoidf_(gz.x + acc0[1][rh * 2]);
                    float z1 = sigmoidf_(gz.y + acc0[1][rh * 2 + 1]);
                    float n0 = tanhf_(gn.x + r0 * (acc0[2][rh * 2] + bhnv.x));
                    float n1 = tanhf_(gn.y + r1 * (acc0[2][rh * 2 + 1] + bhnv.y));
                    hx = n0 + z0 * (hx - n0);
                    hy = n1 + z1 * (hy - n1);
                }
                uint32_t nh, nl;
                split_pack(hx, hy, nh, nl);
                const int wd = (kt * 4 + slot) * 2;
                hb[wd * 128]       = nh;
                hb[(wd + 1) * 128] = nl;
            }
            // ---- stream 1 update (words 32..63) ----
            #pragma unroll
            for (int rh = 0; rh < 2; ++rh) {
                const bool vv = rh ? v11 : v10;
                const float* gp = rh ? gp11 : gp10;
                const int slot = sl + rh;
                float hx = unpk_lo(ah1[kt][slot]) + unpk_lo(al1[kt][slot]);
                float hy = unpk_hi(ah1[kt][slot]) + unpk_hi(al1[kt][slot]);
                if (vv) {
                    float2 gr = *reinterpret_cast<const float2*>(gp + 8 * ntg);
                    float2 gz = *reinterpret_cast<const float2*>(gp + HID + 8 * ntg);
                    float2 gn = *reinterpret_cast<const float2*>(gp + 2 * HID + 8 * ntg);
                    float r0 = sigmoidf_(gr.x + acc1[0][rh * 2]);
                    float r1 = sigmoidf_(gr.y + acc1[0][rh * 2 + 1]);
                    float z0 = sigmoidf_(gz.x + acc1[1][rh * 2]);
                    float z1 = sigmoidf_(gz.y + acc1[1][rh * 2 + 1]);
                    float n0 = tanhf_(gn.x + r0 * (acc1[2][rh * 2] + bhnv.x));
                    float n1 = tanhf_(gn.y + r1 * (acc1[2][rh * 2 + 1] + bhnv.y));
                    hx = n0 + z0 * (hx - n0);
                    hy = n1 + z1 * (hy - n1);
                }
                uint32_t nh, nl;
                split_pack(hx, hy, nh, nl);
                const int wd = 32 + (kt * 4 + slot) * 2;   // FIX: stream 1 at +32
                hb[wd * 128]       = nh;
                hb[(wd + 1) * 128] = nl;
            }
        }

        // reload new h for the next step (own words; program order suffices)
        #pragma unroll
        for (int i = 0; i < 4; ++i)
            #pragma unroll
            for (int jx = 0; jx < 4; ++jx) {
                const int wd = (i * 4 + jx) * 2;
                ah0[i][jx] = hb[wd * 128];
                al0[i][jx] = hb[(wd + 1) * 128];
                ah1[i][jx] = hb[(32 + wd) * 128];          // FIX: +32
                al1[i][jx] = hb[(32 + wd + 1) * 128];
            }
    }

    // ---- re-stage W1 hi/lo into the (now dead) Whh smem region ----
    __syncthreads();
    for (int i = tid; i < HID * HID; i += 128) {
        float v = W1[i];
        int row = i >> 6, col = i & 63;
        uint32_t off = SWZ((uint32_t)(row * 128 + col * 2));
        __nv_bfloat16 hi = __float2bfloat16(v);
        __nv_bfloat16 lo = __float2bfloat16(v - __bfloat162float(hi));
        *reinterpret_cast<__nv_bfloat16*>(smem + OFF_W1_HI + off) = hi;
        *reinterpret_cast<__nv_bfloat16*>(smem + OFF_W1_LO + off) = lo;
    }
    __syncthreads();

    // ---- per-stream MLP + output ----
    #pragma unroll
    for (int s = 0; s < 2; ++s) {
        const uint32_t (*ahp)[4] = s ? ah1 : ah0;
        const uint32_t (*alp)[4] = s ? al1 : al0;
        const int ta = s ? t10 : t00;
        const int tc = s ? t11 : t01;

        float hidv[8][4];
        #pragma unroll
        for (int ntg = 0; ntg < 8; ++ntg) {
            float acc[4] = {0.f, 0.f, 0.f, 0.f};
            #pragma unroll
            for (int kh = 0; kh < 2; ++kh) {
                uint32_t bh[4], bl[4];
                uint32_t boff = SWZ((uint32_t)((ntg * 8 + bn_row) * 128 + (kh * 32 + bn_k) * 2));
                ldsm4(bh, sb + OFF_W1_HI + boff);
                ldsm4(bl, sb + OFF_W1_LO + boff);
                #pragma unroll
                for (int k2 = 0; k2 < 2; ++k2) {
                    const int kt = kh * 2 + k2;
                    mma16816(acc, ahp[kt], bh[k2 * 2], bh[k2 * 2 + 1]);
                    mma16816(acc, alp[kt], bh[k2 * 2], bh[k2 * 2 + 1]);
                    mma16816(acc, ahp[kt], bl[k2 * 2], bl[k2 * 2 + 1]);
                }
            }
            float2 b1v = *reinterpret_cast<const float2*>(&b1[8 * ntg + c2]);
            float h0 = acc[0] + b1v.x, h1 = acc[1] + b1v.y;
            float h2 = acc[2] + b1v.x, h3 = acc[3] + b1v.y;
            hidv[ntg][0] = h0 > 0.f ? h0 : 0.f;
            hidv[ntg][1] = h1 > 0.f ? h1 : 0.f;
            hidv[ntg][2] = h2 > 0.f ? h2 : 0.f;
            hidv[ntg][3] = h3 > 0.f ? h3 : 0.f;
        }

        float po0[4] = {0.f, 0.f, 0.f, 0.f};
        float po1[4] = {0.f, 0.f, 0.f, 0.f};
        #pragma unroll
        for (int ntg = 0; ntg < 8; ++ntg) {
            #pragma unroll
            for (int c = 0; c < 4; ++c) {
                float2 w2v = *reinterpret_cast<const float2*>(&W2[c * HID + 8 * ntg + c2]);
                po0[c] = fmaf(w2v.x, hidv[ntg][0], fmaf(w2v.y, hidv[ntg][1], po0[c]));
                po1[c] = fmaf(w2v.x, hidv[ntg][2], fmaf(w2v.y, hidv[ntg][3], po1[c]));
            }
        }
        #pragma unroll
        for (int c = 0; c < 4; ++c) {
            po0[c] += __shfl_xor_sync(0xffffffffu, po0[c], 1);
            po0[c] += __shfl_xor_sync(0xffffffffu, po0[c], 2);
            po1[c] += __shfl_xor_sync(0xffffffffu, po1[c], 1);
            po1[c] += __shfl_xor_sync(0xffffffffu, po1[c], 2);
        }
        const int c = l & 3;
        if (ta < n) out[ta * DIM_C + c] = po0[c] + b2[c];
        if (tc < n) out[tc * DIM_C + c] = po1[c] + b2[c];
    }
}

// ---------------------------------------------------------------------------
extern "C" void kernel_launch(void* const* d_in, const int* in_sizes, int n_in,
                              void* d_out, int out_size)
{
    const float* emb   = (const float*)d_in[0];
    const float* W_ih  = (const float*)d_in[1];
    const float* W_hh  = (const float*)d_in[2];
    const float* b_ih  = (const float*)d_in[3];
    const float* b_hh  = (const float*)d_in[4];
    const float* W1    = (const float*)d_in[5];
    const float* b1    = (const float*)d_in[6];
    const float* W2    = (const float*)d_in[7];
    const float* b2    = (const float*)d_in[8];
    const int*   dones = (const int*)d_in[9];
    float* out = (float*)d_out;

    int n = in_sizes[0] / D_IN;
    if (n > MAXN) n = MAXN;

    cudaFuncSetAttribute(gru_mma_kernel, cudaFuncAttributeMaxDynamicSharedMemorySize, SMEM_SZ);

    precompute_kernel<<<(n + 63) / 64, 192>>>(emb, W_ih, b_ih, b_hh, dones, n);
    gru_mma_kernel<<<(n + M_TILE - 1) / M_TILE, 128, SMEM_SZ>>>(W_hh, b_hh, W1, b1, W2, b2, out, n);
}

// round 17
// speedup vs baseline: 1.6555x; 1.6555x over previous
#include <cuda_runtime.h>
#include <cuda_bf16.h>
#include <cstdint>

#define LEN_HIS 20
#define D_IN    36
#define HID     64
#define G3      192
#define DIM_C   4
#define MAXN    32768
#define M_TILE  64      // timesteps per block; 4 warps x 16 rows

// ---------------- scratch ----------------
// g_GI layout is PERMUTED per row: pos = q*48 + (gate*8+ntg)*2 + parity,
// where original column j = gate*64 + ntg*8 + 2q + parity. This makes each
// GRU thread's per-step inputs 12 contiguous float4s.
__device__ float g_GI[MAXN * G3];
__device__ int   g_start[MAXN];

// ---------------- smem layout (bytes) ----------------
#define OFF_WHH_HI 0
#define OFF_WHH_LO 24576
#define OFF_W1_HI  49152
#define OFF_W1_LO  57344
#define SMEM_SZ    65536

#define SWZ(o) ((o) ^ (((o) >> 3) & 0x70))

// ---------------- helpers ----------------
__device__ __forceinline__ uint32_t smem_u32(const void* p) {
    uint32_t a;
    asm("{ .reg .u64 t; cvta.to.shared.u64 t, %1; cvt.u32.u64 %0, t; }" : "=r"(a) : "l"(p));
    return a;
}
__device__ __forceinline__ void ldsm4(uint32_t* r, uint32_t addr) {
    asm volatile("ldmatrix.sync.aligned.m8n8.x4.shared.b16 {%0,%1,%2,%3}, [%4];"
        : "=r"(r[0]), "=r"(r[1]), "=r"(r[2]), "=r"(r[3]) : "r"(addr));
}
__device__ __forceinline__ void mma16816(float* d, const uint32_t* a, uint32_t b0, uint32_t b1) {
    asm volatile("mma.sync.aligned.m16n8k16.row.col.f32.bf16.bf16.f32 "
        "{%0,%1,%2,%3}, {%4,%5,%6,%7}, {%8,%9}, {%0,%1,%2,%3};"
        : "+f"(d[0]), "+f"(d[1]), "+f"(d[2]), "+f"(d[3])
        : "r"(a[0]), "r"(a[1]), "r"(a[2]), "r"(a[3]), "r"(b0), "r"(b1));
}
// bf16 split with truncation (x = hi + r exactly; lo = bf16(r) -> ~2^-17 total)
__device__ __forceinline__ void split_pack(float x, float y, uint32_t& hi, uint32_t& lo) {
    uint32_t fx = __float_as_uint(x), fy = __float_as_uint(y);
    hi = (fy & 0xffff0000u) | (fx >> 16);
    float lx = x - __uint_as_float(fx & 0xffff0000u);
    float ly = y - __uint_as_float(fy & 0xffff0000u);
    uint32_t flx = __float_as_uint(lx), fly = __float_as_uint(ly);
    lo = (fly & 0xffff0000u) | (flx >> 16);
}
__device__ __forceinline__ float unpk_lo(uint32_t u) { return __uint_as_float(u << 16); }
__device__ __forceinline__ float unpk_hi(uint32_t u) { return __uint_as_float(u & 0xffff0000u); }

__device__ __forceinline__ float rcpa_(float x) {
    float r;
    asm("rcp.approx.f32 %0, %1;" : "=f"(r) : "f"(x));
    return r;
}
// paired sigmoid: one RCP serves two values (1/a = r*b, 1/b = r*a)
__device__ __forceinline__ float2 sigmoid2_(float x, float y) {
    x = fminf(fmaxf(x, -20.f), 20.f);
    y = fminf(fmaxf(y, -20.f), 20.f);
    float ax = 1.f + __expf(-x);
    float ay = 1.f + __expf(-y);
    float r = rcpa_(ax * ay);
    return make_float2(r * ay, r * ax);
}
// paired tanh: tanh(v) = 2/(1+e^-2v) - 1
__device__ __forceinline__ float2 tanh2_(float x, float y) {
    x = fminf(fmaxf(x, -15.f), 15.f);
    y = fminf(fmaxf(y, -15.f), 15.f);
    float ax = 1.f + __expf(-2.f * x);
    float ay = 1.f + __expf(-2.f * y);
    float r = rcpa_(ax * ay);
    return make_float2(fmaf(2.f * ay, r, -1.f), fmaf(2.f * ax, r, -1.f));
}

// ---------------------------------------------------------------------------
// Kernel A: GI[t][pos(j)] = b_ih[j] + (j<128 ? b_hh[j] : 0) + emb[t].W_ih[j]
//           written in the PERMUTED fragment layout; plus window starts.
// ---------------------------------------------------------------------------
__global__ void __launch_bounds__(192) precompute_kernel(
    const float* __restrict__ emb, const float* __restrict__ W_ih,
    const float* __restrict__ b_ih, const float* __restrict__ b_hh,
    const int* __restrict__ dones, int n)
{
    __shared__ float sW[D_IN * G3];
    __shared__ float sX[64 * D_IN];
    const int tid = threadIdx.x;
    const int t0  = blockIdx.x * 64;

    for (int idx = tid; idx < G3 * D_IN; idx += 192) {
        int j = idx / D_IN, k = idx % D_IN;
        sW[k * G3 + j] = W_ih[idx];
    }
    const int nt = min(64, n - t0);
    for (int idx = tid; idx < nt * D_IN; idx += 192)
        sX[idx] = emb[t0 * D_IN + idx];
    __syncthreads();

    // permuted destination for column j = tid
    const int gate = tid >> 6;
    const int jc   = tid & 63;
    const int ntgi = jc >> 3;
    const int q    = (jc & 7) >> 1;
    const int par  = jc & 1;
    const int pos  = q * 48 + (gate * 8 + ntgi) * 2 + par;

    const float bj = b_ih[tid] + (tid < 128 ? b_hh[tid] : 0.f);
    for (int tt = 0; tt < nt; ++tt) {
        float a0 = bj, a1 = 0.f, a2 = 0.f, a3 = 0.f;
        const float* x = &sX[tt * D_IN];
        #pragma unroll
        for (int k = 0; k < 36; k += 4) {
            a0 = fmaf(sW[(k + 0) * G3 + tid], x[k + 0], a0);
            a1 = fmaf(sW[(k + 1) * G3 + tid], x[k + 1], a1);
            a2 = fmaf(sW[(k + 2) * G3 + tid], x[k + 2], a2);
            a3 = fmaf(sW[(k + 3) * G3 + tid], x[k + 3], a3);
        }
        g_GI[(t0 + tt) * G3 + pos] = (a0 + a1) + (a2 + a3);
    }

    if (tid < 64) {
        int t = t0 + tid;
        if (t < n) {
            int s = t - (LEN_HIS - 1);
            if (s < 0) s = 0;
            int st = s;
            for (int k = s; k < t; ++k)
                if (dones[k] != 0) st = k + 1;
            g_start[t] = st;
        }
    }
}

// ---------------------------------------------------------------------------
// Kernel B: warp-MMA batched GRU (R7 structure). ntg processed in PAIRS:
// all 6 GI float4 loads for the pair issue before the pair's MMA bursts so
// L2 latency hides under tensor work. Gate nonlinearities use paired-RCP
// (one MUFU rcp per two lanes). Register double-buffered h.
// ---------------------------------------------------------------------------
__global__ void __launch_bounds__(128) gru_mma_kernel(
    const float* __restrict__ Whh, const float* __restrict__ bhh,
    const float* __restrict__ W1,  const float* __restrict__ b1,
    const float* __restrict__ W2,  const float* __restrict__ b2,
    float* __restrict__ out, int n)
{
    extern __shared__ __align__(1024) char smem[];
    const int tid = threadIdx.x;
    const int l   = tid & 31;
    const int w   = tid >> 5;

    // stage Whh (192x64) and W1 (64x64) hi/lo, SW128-swizzled 128B rows
    for (int i = tid; i < G3 * HID; i += 128) {
        float v = Whh[i];
        int row = i >> 6, col = i & 63;
        uint32_t off = SWZ((uint32_t)(row * 128 + col * 2));
        __nv_bfloat16 hi = __float2bfloat16(v);
        __nv_bfloat16 lo = __float2bfloat16(v - __bfloat162float(hi));
        *reinterpret_cast<__nv_bfloat16*>(smem + OFF_WHH_HI + off) = hi;
        *reinterpret_cast<__nv_bfloat16*>(smem + OFF_WHH_LO + off) = lo;
    }
    for (int i = tid; i < HID * HID; i += 128) {
        float v = W1[i];
        int row = i >> 6, col = i & 63;
        uint32_t off = SWZ((uint32_t)(row * 128 + col * 2));
        __nv_bfloat16 hi = __float2bfloat16(v);
        __nv_bfloat16 lo = __float2bfloat16(v - __bfloat162float(hi));
        *reinterpret_cast<__nv_bfloat16*>(smem + OFF_W1_HI + off) = hi;
        *reinterpret_cast<__nv_bfloat16*>(smem + OFF_W1_LO + off) = lo;
    }
    __syncthreads();

    const uint32_t sb = smem_u32(smem);
    const int q  = (l & 3);                       // quad column group
    const int c2 = q * 2;                         // col pair within 8-wide tile
    const int t0 = blockIdx.x * M_TILE + w * 16 + (l >> 2);
    const int t1 = t0 + 8;
    const int start0 = (t0 < n) ? g_start[t0] : 0;
    const int start1 = (t1 < n) ? g_start[t1] : 0;

    int first0 = (t0 < n) ? max(0, start0 - t0 + (LEN_HIS - 1)) : LEN_HIS;
    int first1 = (t1 < n) ? max(0, start1 - t1 + (LEN_HIS - 1)) : LEN_HIS;
    const int warp_first = __reduce_min_sync(0xffffffffu, min(first0, first1));

    // b_hh for the n-gate at my column pairs
    float2 bhn[8];
    #pragma unroll
    for (int g = 0; g < 8; ++g)
        bhn[g] = *reinterpret_cast<const float2*>(&bhh[2 * HID + 8 * g + c2]);

    // ldmatrix address pieces for B tiles
    const int bn_row = (l & 7);
    const int bn_k   = (l >> 3) * 8;

    // hidden-state A fragments: [k-tile 0..3][a0..a3], bf16x2 packed
    uint32_t a_hi[4][4], a_lo[4][4];
    #pragma unroll
    for (int i = 0; i < 4; ++i)
        #pragma unroll
        for (int jx = 0; jx < 4; ++jx) { a_hi[i][jx] = 0u; a_lo[i][jx] = 0u; }

    for (int step = warp_first; step < LEN_HIS; ++step) {
        const int g0 = t0 - (LEN_HIS - 1) + step;
        const int g1 = t1 - (LEN_HIS - 1) + step;
        const bool v0 = (t0 < n) && (g0 >= start0);
        const bool v1 = (t1 < n) && (g1 >= start1);
        // permuted-layout base: 12 float4s per thread per row
        const float4* gq0 = reinterpret_cast<const float4*>(&g_GI[(v0 ? g0 : 0) * G3]) + q * 12;
        const float4* gq1 = reinterpret_cast<const float4*>(&g_GI[(v1 ? g1 : 0) * G3]) + q * 12;

        uint32_t n_hi[4][4], n_lo[4][4];   // NEW h (double buffer)

        #pragma unroll
        for (int ntgp = 0; ntgp < 4; ++ntgp) {
            // hoisted GI loads for this ntg pair (both row-halves): 6x LDG.128
            const float4 r40 = gq0[ntgp],     z40 = gq0[4 + ntgp], n40 = gq0[8 + ntgp];
            const float4 r41 = gq1[ntgp],     z41 = gq1[4 + ntgp], n41 = gq1[8 + ntgp];

            #pragma unroll
            for (int sub = 0; sub < 2; ++sub) {
                const int ntg = ntgp * 2 + sub;
                float acc[3][4];
                #pragma unroll
                for (int gi = 0; gi < 3; ++gi)
                    #pragma unroll
                    for (int ci = 0; ci < 4; ++ci) acc[gi][ci] = 0.f;

                #pragma unroll
                for (int gate = 0; gate < 3; ++gate) {
                    const int nt = gate * 8 + ntg;
                    #pragma unroll
                    for (int kh = 0; kh < 2; ++kh) {
                        uint32_t bh[4], bl[4];
                        uint32_t boff = SWZ((uint32_t)((nt * 8 + bn_row) * 128 + (kh * 32 + bn_k) * 2));
                        ldsm4(bh, sb + OFF_WHH_HI + boff);
                        ldsm4(bl, sb + OFF_WHH_LO + boff);
                        #pragma unroll
                        for (int k2 = 0; k2 < 2; ++k2) {
                            const int kt = kh * 2 + k2;
                            mma16816(acc[gate], a_hi[kt], bh[k2 * 2], bh[k2 * 2 + 1]); // hi*hi
                            mma16816(acc[gate], a_lo[kt], bh[k2 * 2], bh[k2 * 2 + 1]); // lo*hi
                            mma16816(acc[gate], a_hi[kt], bl[k2 * 2], bl[k2 * 2 + 1]); // hi*lo
                        }
                    }
                }

                // gate update into the double buffer (reads only OLD fragments)
                const int kt = ntg >> 1;
                const int sl = (ntg & 1) * 2;
                #pragma unroll
                for (int rh = 0; rh < 2; ++rh) {
                    const bool vv = rh ? v1 : v0;
                    const int slot = sl + rh;
                    float hx = unpk_lo(a_hi[kt][slot]) + unpk_lo(a_lo[kt][slot]);
                    float hy = unpk_hi(a_hi[kt][slot]) + unpk_hi(a_lo[kt][slot]);
                    if (vv) {
                        const float4& r4 = rh ? r41 : r40;
                        const float4& z4 = rh ? z41 : z40;
                        const float4& n4 = rh ? n41 : n40;
                        const float grx = sub ? r4.z : r4.x, gry = sub ? r4.w : r4.y;
                        const float gzx = sub ? z4.z : z4.x, gzy = sub ? z4.w : z4.y;
                        const float gnx = sub ? n4.z : n4.x, gny = sub ? n4.w : n4.y;
                        const float ar0 = acc[0][rh * 2], ar1 = acc[0][rh * 2 + 1];
                        const float az0 = acc[1][rh * 2], az1 = acc[1][rh * 2 + 1];
                        const float an0 = acc[2][rh * 2], an1 = acc[2][rh * 2 + 1];
                        float2 rr = sigmoid2_(grx + ar0, gry + ar1);
                        float2 zz = sigmoid2_(gzx + az0, gzy + az1);
                        float2 nn = tanh2_(gnx + rr.x * (an0 + bhn[ntg].x),
                                           gny + rr.y * (an1 + bhn[ntg].y));
                        hx = nn.x + zz.x * (hx - nn.x);
                        hy = nn.y + zz.y * (hy - nn.y);
                    }
                    split_pack(hx, hy, n_hi[kt][slot], n_lo[kt][slot]);
                }
            }
        }

        // commit new h for the next step
        #pragma unroll
        for (int i = 0; i < 4; ++i)
            #pragma unroll
            for (int jx = 0; jx < 4; ++jx) {
                a_hi[i][jx] = n_hi[i][jx];
                a_lo[i][jx] = n_lo[i][jx];
            }
    }

    // ---- MLP layer 1 via MMA: hid = relu(h @ W1^T + b1) ----
    float hidv[8][4];
    #pragma unroll
    for (int ntg = 0; ntg < 8; ++ntg) {
        float acc[4] = {0.f, 0.f, 0.f, 0.f};
        #pragma unroll
        for (int kh = 0; kh < 2; ++kh) {
            uint32_t bh[4], bl[4];
            uint32_t boff = SWZ((uint32_t)((ntg * 8 + bn_row) * 128 + (kh * 32 + bn_k) * 2));
            ldsm4(bh, sb + OFF_W1_HI + boff);
            ldsm4(bl, sb + OFF_W1_LO + boff);
            #pragma unroll
            for (int k2 = 0; k2 < 2; ++k2) {
                const int kt = kh * 2 + k2;
                mma16816(acc, a_hi[kt], bh[k2 * 2], bh[k2 * 2 + 1]);
                mma16816(acc, a_lo[kt], bh[k2 * 2], bh[k2 * 2 + 1]);
                mma16816(acc, a_hi[kt], bl[k2 * 2], bl[k2 * 2 + 1]);
            }
        }
        float2 b1v = *reinterpret_cast<const float2*>(&b1[8 * ntg + c2]);
        float h0 = acc[0] + b1v.x, h1 = acc[1] + b1v.y;
        float h2 = acc[2] + b1v.x, h3 = acc[3] + b1v.y;
        hidv[ntg][0] = h0 > 0.f ? h0 : 0.f;
        hidv[ntg][1] = h1 > 0.f ? h1 : 0.f;
        hidv[ntg][2] = h2 > 0.f ? h2 : 0.f;
        hidv[ntg][3] = h3 > 0.f ? h3 : 0.f;
    }

    // ---- out = W2 @ hid + b2 (scalar partials + quad butterfly reduce) ----
    float po0[4] = {0.f, 0.f, 0.f, 0.f};
    float po1[4] = {0.f, 0.f, 0.f, 0.f};
    #pragma unroll
    for (int ntg = 0; ntg < 8; ++ntg) {
        #pragma unroll
        for (int c = 0; c < 4; ++c) {
            float2 w2v = *reinterpret_cast<const float2*>(&W2[c * HID + 8 * ntg + c2]);
            po0[c] = fmaf(w2v.x, hidv[ntg][0], fmaf(w2v.y, hidv[ntg][1], po0[c]));
            po1[c] = fmaf(w2v.x, hidv[ntg][2], fmaf(w2v.y, hidv[ntg][3], po1[c]));
        }
    }
    #pragma unroll
    for (int c = 0; c < 4; ++c) {
        po0[c] += __shfl_xor_sync(0xffffffffu, po0[c], 1);
        po0[c] += __shfl_xor_sync(0xffffffffu, po0[c], 2);
        po1[c] += __shfl_xor_sync(0xffffffffu, po1[c], 1);
        po1[c] += __shfl_xor_sync(0xffffffffu, po1[c], 2);
    }
    const int c = l & 3;
    if (t0 < n) out[t0 * DIM_C + c] = po0[c] + b2[c];
    if (t1 < n) out[t1 * DIM_C + c] = po1[c] + b2[c];
}

// ---------------------------------------------------------------------------
extern "C" void kernel_launch(void* const* d_in, const int* in_sizes, int n_in,
                              void* d_out, int out_size)
{
    const float* emb   = (const float*)d_in[0];
    const float* W_ih  = (const float*)d_in[1];
    const float* W_hh  = (const float*)d_in[2];
    const float* b_ih  = (const float*)d_in[3];
    const float* b_hh  = (const float*)d_in[4];
    const float* W1    = (const float*)d_in[5];
    const float* b1    = (const float*)d_in[6];
    const float* W2    = (const float*)d_in[7];
    const float* b2    = (const float*)d_in[8];
    const int*   dones = (const int*)d_in[9];
    float* out = (float*)d_out;

    int n = in_sizes[0] / D_IN;
    if (n > MAXN) n = MAXN;

    cudaFuncSetAttribute(gru_mma_kernel, cudaFuncAttributeMaxDynamicSharedMemorySize, SMEM_SZ);

    precompute_kernel<<<(n + 63) / 64, 192>>>(emb, W_ih, b_ih, b_hh, dones, n);
    gru_mma_kernel<<<(n + M_TILE - 1) / M_TILE, 128, SMEM_SZ>>>(W_hh, b_hh, W1, b1, W2, b2, out, n);
}